// round 2
// baseline (speedup 1.0000x reference)
#include <cuda_runtime.h>
#include <math.h>

#define N    8192
#define FIN  128
#define FOUT 64
#define RI   16      // rows per block in main kernel
#define TJ   128     // j-chunk size

// Scratch (allocation-free rule: __device__ globals)
__device__ __align__(128) float g_Wh[N * FOUT];   // x @ W^T
__device__ __align__(128) float g_B1[N];          // exp(Wh2[j])
__device__ __align__(128) float g_B2[N];          // exp(0.2*Wh2[j])
__device__ __align__(128) float g_w1[N];          // Wh1[i]
__device__ __align__(128) float g_r[N];           // exp(-0.8*Wh1[i])
__device__ __align__(128) float g_Wh2[N];         // Wh2[j]

// ---------------------------------------------------------------------------
// Kernel 1: Wh = x @ W^T.  4 rows per block, W transposed into smem.
// ---------------------------------------------------------------------------
__global__ void k_wh(const float* __restrict__ x, const float* __restrict__ W) {
    __shared__ float Wt[FIN * FOUT];   // [c][k], conflict-free reads (k = lane)
    __shared__ float xs[4 * FIN];
    const int t = threadIdx.x;         // 256 threads
    const int row0 = blockIdx.x * 4;

    for (int idx = t; idx < FIN * FOUT; idx += 256) {
        int k = idx >> 7;       // W is [FOUT][FIN] row-major
        int c = idx & 127;
        Wt[c * FOUT + k] = W[idx];
    }
    for (int idx = t; idx < 4 * FIN; idx += 256)
        xs[idx] = x[(size_t)row0 * FIN + idx];
    __syncthreads();

    const int r = t >> 6;   // 0..3
    const int k = t & 63;   // 0..63
    float acc = 0.f;
#pragma unroll 16
    for (int c = 0; c < FIN; c++)
        acc = fmaf(xs[r * FIN + c], Wt[c * FOUT + k], acc);
    g_Wh[(size_t)(row0 + r) * FOUT + k] = acc;
}

// ---------------------------------------------------------------------------
// Kernel 2: per-row scalars  Wh1, Wh2 -> r, B1, B2.  One warp per row.
// ---------------------------------------------------------------------------
__global__ void k_rows(const float* __restrict__ a) {
    const int i = blockIdx.x * 8 + threadIdx.y;   // blockDim = (32, 8)
    const int lane = threadIdx.x;
    const float v0 = g_Wh[(size_t)i * FOUT + lane];
    const float v1 = g_Wh[(size_t)i * FOUT + 32 + lane];
    float s1 = v0 * a[lane]      + v1 * a[32 + lane];   // Wh . a1
    float s2 = v0 * a[64 + lane] + v1 * a[96 + lane];   // Wh . a2
#pragma unroll
    for (int o = 16; o; o >>= 1) {
        s1 += __shfl_xor_sync(0xffffffffu, s1, o);
        s2 += __shfl_xor_sync(0xffffffffu, s2, o);
    }
    if (lane == 0) {
        g_w1[i]  = s1;
        g_r[i]   = expf(-0.8f * s1);
        g_Wh2[i] = s2;
        g_B1[i]  = expf(s2);
        g_B2[i]  = expf(0.2f * s2);
    }
}

__device__ __forceinline__ float elu_f(float v) {
    return v > 0.f ? v : expm1f(v);
}

// ---------------------------------------------------------------------------
// Kernel 3: main fused masked-softmax-matmul.
// Block: 128 threads, RI=16 rows, j processed in TJ=128 chunks.
//  Phase A: 16 rows x 8 slots; each thread computes 16 masked weights q, STS.
//  Phase B: warp = 4 rows x 8 col-groups; thread owns cols [4cg,4cg+4) and
//           [32+4cg, 32+4cg+4)  (disjoint-bank LDS.128 pattern).
// ---------------------------------------------------------------------------
__global__ void __launch_bounds__(128, 4) k_main(const int* __restrict__ adj,
                                                 float* __restrict__ out) {
    __shared__ float Wh_s[TJ * FOUT];          // 32 KB
    __shared__ float q_s[RI][TJ + 4];          // padded pitch: conflict-free
    __shared__ float w1_s[RI], r_s[RI];
    __shared__ float dsum[RI][9];

    const int t = threadIdx.x;
    const int row0 = blockIdx.x * RI;

    if (t < RI) { w1_s[t] = g_w1[row0 + t]; r_s[t] = g_r[row0 + t]; }
    __syncthreads();

    // phase A mapping
    const int ruA = t >> 3;           // 0..15
    const int slA = t & 7;            // 0..7 (16 j's each)
    const float w1A = w1_s[ruA];
    const float rA  = r_s[ruA];
    const size_t adj_row = (size_t)(row0 + ruA) * N;

    // phase B mapping
    const int rowB = ((t >> 5) << 2) + ((t >> 3) & 3);  // 0..15
    const int cg   = t & 7;                              // 0..7

    float acc[8];
#pragma unroll
    for (int u = 0; u < 8; u++) acc[u] = 0.f;
    float dpart = 0.f;

    for (int jb = 0; jb < N; jb += TJ) {
        // stage Wh chunk: 8192 floats = 2048 float4, 128 threads x 16
        {
            const float4* src = (const float4*)(g_Wh + (size_t)jb * FOUT);
            float4* dst = (float4*)Wh_s;
#pragma unroll
            for (int u = 0; u < 16; u++)
                dst[t + u * 128] = src[t + u * 128];
        }

        // phase A: masked weights q for this block's 16 rows x 128 j
        const int j0 = jb + slA * 16;
#pragma unroll
        for (int u = 0; u < 4; u++) {
            const int jj = slA * 16 + u * 4;
            int4 m = __ldcs((const int4*)(adj + adj_row + (size_t)jb + jj));
            float4 b1 = *(const float4*)(g_B1  + j0 + u * 4);
            float4 b2 = *(const float4*)(g_B2  + j0 + u * 4);
            float4 h2 = *(const float4*)(g_Wh2 + j0 + u * 4);
            float q0 = (w1A + h2.x > 0.f) ? b1.x : rA * b2.x; if (!m.x) q0 = 0.f;
            float q1 = (w1A + h2.y > 0.f) ? b1.y : rA * b2.y; if (!m.y) q1 = 0.f;
            float q2 = (w1A + h2.z > 0.f) ? b1.z : rA * b2.z; if (!m.z) q2 = 0.f;
            float q3 = (w1A + h2.w > 0.f) ? b1.w : rA * b2.w; if (!m.w) q3 = 0.f;
            dpart += q0 + q1 + q2 + q3;
            q_s[ruA][jj + 0] = q0;
            q_s[ruA][jj + 1] = q1;
            q_s[ruA][jj + 2] = q2;
            q_s[ruA][jj + 3] = q3;
        }
        __syncthreads();

        // phase B: acc += q * Wh[j]
        const float4* whp = (const float4*)Wh_s;
#pragma unroll 4
        for (int jj = 0; jj < TJ; jj++) {
            const float q = q_s[rowB][jj];
            const float4 wa = whp[jj * 16 + cg];
            const float4 wb = whp[jj * 16 + 8 + cg];
            acc[0] = fmaf(q, wa.x, acc[0]);
            acc[1] = fmaf(q, wa.y, acc[1]);
            acc[2] = fmaf(q, wa.z, acc[2]);
            acc[3] = fmaf(q, wa.w, acc[3]);
            acc[4] = fmaf(q, wb.x, acc[4]);
            acc[5] = fmaf(q, wb.y, acc[5]);
            acc[6] = fmaf(q, wb.z, acc[6]);
            acc[7] = fmaf(q, wb.w, acc[7]);
        }
        __syncthreads();
    }

    // denominator reduction (phase-A layout -> per-row)
    dsum[ruA][slA] = dpart;
    __syncthreads();
    if (t < RI) {
        float d = 0.f;
#pragma unroll
        for (int s = 0; s < 8; s++) d += dsum[t][s];
        dsum[t][8] = d;
    }
    __syncthreads();

    const float inv = 1.0f / dsum[rowB][8];
    float* op = out + (size_t)(row0 + rowB) * FOUT + cg * 4;
    float4 o0, o1;
    o0.x = elu_f(acc[0] * inv);
    o0.y = elu_f(acc[1] * inv);
    o0.z = elu_f(acc[2] * inv);
    o0.w = elu_f(acc[3] * inv);
    o1.x = elu_f(acc[4] * inv);
    o1.y = elu_f(acc[5] * inv);
    o1.z = elu_f(acc[6] * inv);
    o1.w = elu_f(acc[7] * inv);
    *(float4*)op        = o0;
    *(float4*)(op + 32) = o1;
}

// ---------------------------------------------------------------------------
extern "C" void kernel_launch(void* const* d_in, const int* in_sizes, int n_in,
                              void* d_out, int out_size) {
    const float* x   = (const float*)d_in[0];
    const int*   adj = (const int*)d_in[1];
    const float* W   = (const float*)d_in[2];
    const float* a   = (const float*)d_in[3];
    float* out = (float*)d_out;

    k_wh<<<N / 4, 256>>>(x, W);
    k_rows<<<N / 8, dim3(32, 8)>>>(a);
    k_main<<<N / RI, 128>>>(adj, out);
}

// round 5
// speedup vs baseline: 7.0690x; 7.0690x over previous
#include <cuda_runtime.h>
#include <cuda_fp16.h>
#include <math.h>
#include <stdint.h>

#define NV    8192
#define FOUT  64
#define NP    72          // padded N: 64 feats + col64 = denominator + pad
#define JSPL  4
#define JW    (NV / JSPL) // 2048 j per CTA
#define CJ    128         // j chunk staged in smem
#define NCH   (JW / CJ)   // 16 chunks

// ------------------------- device scratch (no allocs) -----------------------
__device__ __align__(128) float  g_Wh[NV * FOUT];
__device__ __align__(128) __half g_U[NV * NP];     // [j][72]: B1*Wh, col64=B1
__device__ __align__(128) __half g_V[NV * NP];     // [j][72]: B2*Wh, col64=B2
__device__ __align__(128) __half g_w1h[NV];        // fp16(-Wh1[i])  (threshold)
__device__ __align__(128) __half g_w2h[NV];        // fp16(Wh2[j])
__device__ __align__(128) float  g_r[NV];          // exp(-0.8*Wh1[i])
__device__ __align__(128) float  g_pnum[JSPL * NV * NP];  // partials (col64=den)

// ------------------------- small PTX helpers --------------------------------
__device__ __forceinline__ uint32_t smem_u32(const void* p) {
    uint32_t a;
    asm("{ .reg .u64 t; cvta.to.shared.u64 t, %1; cvt.u32.u64 %0, t; }" : "=r"(a) : "l"(p));
    return a;
}
__device__ __forceinline__ void cpa16(uint32_t dst, const void* src) {
    asm volatile("cp.async.cg.shared.global [%0], [%1], 16;" :: "r"(dst), "l"(src));
}
#define CP_COMMIT() asm volatile("cp.async.commit_group;")
#define CP_WAIT0()  asm volatile("cp.async.wait_group 0;")

__device__ __forceinline__ void ldsm4t(uint32_t* r, uint32_t addr) {
    asm volatile("ldmatrix.sync.aligned.m8n8.x4.trans.shared.b16 {%0,%1,%2,%3}, [%4];"
                 : "=r"(r[0]), "=r"(r[1]), "=r"(r[2]), "=r"(r[3]) : "r"(addr));
}
__device__ __forceinline__ void ldsm2t(uint32_t* r, uint32_t addr) {
    asm volatile("ldmatrix.sync.aligned.m8n8.x2.trans.shared.b16 {%0,%1}, [%2];"
                 : "=r"(r[0]), "=r"(r[1]) : "r"(addr));
}
__device__ __forceinline__ void mma16816(float* d, const uint32_t* a, const uint32_t* b) {
    asm volatile("mma.sync.aligned.m16n8k16.row.col.f32.f16.f16.f32 "
                 "{%0,%1,%2,%3}, {%4,%5,%6,%7}, {%8,%9}, {%0,%1,%2,%3};"
                 : "+f"(d[0]), "+f"(d[1]), "+f"(d[2]), "+f"(d[3])
                 : "r"(a[0]), "r"(a[1]), "r"(a[2]), "r"(a[3]), "r"(b[0]), "r"(b[1]));
}
__device__ __forceinline__ uint32_t hgt2_mask(uint32_t w2, uint32_t th) {
    __half2 a = *(__half2*)&w2, b = *(__half2*)&th;
    __half2 s = __hgt2(a, b);              // 1.0 / 0.0 per half  (0x3C00 codes)
    return *(uint32_t*)&s;
}

// ---------------------------------------------------------------------------
// Kernel 1: Wh = x @ W^T   (fp32, register tiled)
// ---------------------------------------------------------------------------
__global__ void __launch_bounds__(256) k_wh(const float* __restrict__ x,
                                            const float* __restrict__ W) {
    __shared__ float xs[16 * 128];
    __shared__ float wt[64 * 132];
    const int t = threadIdx.x;
    const int row0 = blockIdx.x * 16;

    for (int i4 = t; i4 < 2048; i4 += 256) {
        int k = i4 >> 5, c4 = i4 & 31;
        float4 v = ((const float4*)W)[i4];
        *(float4*)&wt[k * 132 + c4 * 4] = v;
    }
    for (int i4 = t; i4 < 512; i4 += 256)
        ((float4*)xs)[i4] = ((const float4*)(x + (size_t)row0 * 128))[i4];
    __syncthreads();

    const int k = t & 63, rg = t >> 6;
    float acc[4] = {0.f, 0.f, 0.f, 0.f};
#pragma unroll 8
    for (int c4 = 0; c4 < 32; c4++) {
        float4 w = *(const float4*)&wt[k * 132 + c4 * 4];
#pragma unroll
        for (int u = 0; u < 4; u++) {
            float4 xv = *(const float4*)&xs[(rg * 4 + u) * 128 + c4 * 4];
            acc[u] = fmaf(xv.x, w.x, acc[u]);
            acc[u] = fmaf(xv.y, w.y, acc[u]);
            acc[u] = fmaf(xv.z, w.z, acc[u]);
            acc[u] = fmaf(xv.w, w.w, acc[u]);
        }
    }
#pragma unroll
    for (int u = 0; u < 4; u++)
        g_Wh[(size_t)(row0 + rg * 4 + u) * FOUT + k] = acc[u];
}

// ---------------------------------------------------------------------------
// Kernel 2: per-index scalars + U/V fp16 tables [j][72]
// ---------------------------------------------------------------------------
__global__ void __launch_bounds__(128) k_prep(const float* __restrict__ a) {
    __shared__ float a_s[128];
    const int t = threadIdx.x;
    if (t < 128) a_s[t] = a[t];
    __syncthreads();

    const int j = blockIdx.x * 128 + t;
    float wh[64];
    float s1 = 0.f, s2 = 0.f;
#pragma unroll
    for (int f4 = 0; f4 < 16; f4++) {
        float4 v = ((const float4*)(g_Wh + (size_t)j * FOUT))[f4];
        wh[f4 * 4 + 0] = v.x; wh[f4 * 4 + 1] = v.y;
        wh[f4 * 4 + 2] = v.z; wh[f4 * 4 + 3] = v.w;
        s1 = fmaf(v.x, a_s[f4 * 4 + 0], s1); s2 = fmaf(v.x, a_s[64 + f4 * 4 + 0], s2);
        s1 = fmaf(v.y, a_s[f4 * 4 + 1], s1); s2 = fmaf(v.y, a_s[64 + f4 * 4 + 1], s2);
        s1 = fmaf(v.z, a_s[f4 * 4 + 2], s1); s2 = fmaf(v.z, a_s[64 + f4 * 4 + 2], s2);
        s1 = fmaf(v.w, a_s[f4 * 4 + 3], s1); s2 = fmaf(v.w, a_s[64 + f4 * 4 + 3], s2);
    }
    const float B1 = expf(s2), B2 = expf(0.2f * s2);
    g_w1h[j] = __float2half(-s1);
    g_w2h[j] = __float2half(s2);
    g_r[j]   = expf(-0.8f * s1);

    __half2* U = (__half2*)(g_U + (size_t)j * NP);
    __half2* V = (__half2*)(g_V + (size_t)j * NP);
#pragma unroll
    for (int f2 = 0; f2 < 32; f2++) {
        U[f2] = __floats2half2_rn(B1 * wh[f2 * 2], B1 * wh[f2 * 2 + 1]);
        V[f2] = __floats2half2_rn(B2 * wh[f2 * 2], B2 * wh[f2 * 2 + 1]);
    }
    U[32] = __floats2half2_rn(B1, 0.f);
    V[32] = __floats2half2_rn(B2, 0.f);
#pragma unroll
    for (int f2 = 33; f2 < 36; f2++) { U[f2] = __floats2half2_rn(0.f, 0.f); V[f2] = __floats2half2_rn(0.f, 0.f); }
}

// ---------------------------------------------------------------------------
// Kernel 3: main — register-built 0/1 fragments + mma.sync f16 chains
// grid = 256 (64 row-blocks x 4 j-splits), 256 threads (8 warps x 16 rows)
// ---------------------------------------------------------------------------
#define SM_U   0
#define SM_V   36864
#define SM_W2  73728
#define SM_MAIN 74240

__global__ void __launch_bounds__(256, 2) k_main(const int* __restrict__ adj) {
    extern __shared__ char sm[];
    const uint32_t smb = smem_u32(sm);
    const int t = threadIdx.x;
    const int w = t >> 5, l = t & 31;
    const int rb = blockIdx.x >> 2;          // row-block 0..63
    const int js = blockIdx.x & 3;           // j-split 0..3
    const int rt0 = rb * 128;
    const int jb0 = js * JW;

    const int l2 = (l & 3) * 2;
    const int rowA = rt0 + w * 16 + (l >> 2);
    const int rowB = rowA + 8;
    const int* pa0 = adj + (size_t)rowA * NV + jb0 + l2;
    const int* pa1 = adj + (size_t)rowB * NV + jb0 + l2;

    // thresholds (broadcast half2)
    const uint16_t t0 = *(const uint16_t*)&g_w1h[rowA];
    const uint16_t t1 = *(const uint16_t*)&g_w1h[rowB];
    const uint32_t th0 = (uint32_t)t0 | ((uint32_t)t0 << 16);
    const uint32_t th1 = (uint32_t)t1 | ((uint32_t)t1 << 16);

    float dU[36], dV[36];
#pragma unroll
    for (int i = 0; i < 36; i++) { dU[i] = 0.f; dV[i] = 0.f; }

    // ---- staging lambda: chunk jc (global j), into buffer buf ----
    auto stage = [&](int buf, int jc) {
#pragma unroll
        for (int i = 0; i < 9; i++) {
            const int idx = t + i * 256;             // 0..2303
            const int hs = idx >= 1152;              // 0:U  1:V
            const int line = idx - hs * 1152;
            const int row = line / 9, seg = line - row * 9;
            const uint32_t dst = smb + (hs ? SM_V : SM_U) + buf * 18432 + row * 144 + seg * 16;
            const char* src = (const char*)(hs ? g_V : g_U) + (size_t)(jc + row) * 144 + seg * 16;
            cpa16(dst, src);
        }
        if (t < 16)
            cpa16(smb + SM_W2 + buf * 256 + t * 16, (const char*)g_w2h + (size_t)jc * 2 + t * 16);
        CP_COMMIT();
    };

    stage(0, jb0);

    for (int c = 0; c < NCH; c++) {
        const int buf = c & 1;
        CP_WAIT0();
        __syncthreads();
        if (c + 1 < NCH) stage((c + 1) & 1, jb0 + (c + 1) * CJ);

        const uint32_t bu_base = smb + SM_U + buf * 18432;
        const uint32_t bv_base = smb + SM_V + buf * 18432;
        const uint32_t w2_base = smb + SM_W2 + buf * 256;
        const int coff = c * CJ;

#pragma unroll
        for (int kk = 0; kk < 8; kk++) {
            const int jo = coff + kk * 16;
            int2 mA0 = __ldcs((const int2*)(pa0 + jo));
            int2 mA1 = __ldcs((const int2*)(pa0 + jo + 8));
            int2 mB0 = __ldcs((const int2*)(pa1 + jo));
            int2 mB1 = __ldcs((const int2*)(pa1 + jo + 8));

            const uint32_t w2lo = *(const uint32_t*)(sm + (w2_base - smb) + (kk * 16 + l2) * 2);
            const uint32_t w2hi = *(const uint32_t*)(sm + (w2_base - smb) + (kk * 16 + l2 + 8) * 2);

            const uint32_t MA0 = (uint32_t)mA0.x * 0x3C00u + (uint32_t)mA0.y * 0x3C000000u;
            const uint32_t MA1 = (uint32_t)mA1.x * 0x3C00u + (uint32_t)mA1.y * 0x3C000000u;
            const uint32_t MB0 = (uint32_t)mB0.x * 0x3C00u + (uint32_t)mB0.y * 0x3C000000u;
            const uint32_t MB1 = (uint32_t)mB1.x * 0x3C00u + (uint32_t)mB1.y * 0x3C000000u;

            const uint32_t sAlo = hgt2_mask(w2lo, th0);
            const uint32_t sAhi = hgt2_mask(w2hi, th0);
            const uint32_t sBlo = hgt2_mask(w2lo, th1);
            const uint32_t sBhi = hgt2_mask(w2hi, th1);

            uint32_t A[4], C[4];
            A[0] = MA0 & sAlo;  A[1] = MB0 & sBlo;
            A[2] = MA1 & sAhi;  A[3] = MB1 & sBhi;
            C[0] = A[0] ^ MA0;  C[1] = A[1] ^ MB0;
            C[2] = A[2] ^ MA1;  C[3] = A[3] ^ MB1;

            const int krow = kk * 16 + ((l >> 3) & 1) * 8 + (l & 7);
            const uint32_t cadd = (uint32_t)((l >> 4) * 8) * 2;

#pragma unroll
            for (int nt2 = 0; nt2 < 4; nt2++) {
                uint32_t b[4];
                const uint32_t co = (uint32_t)(nt2 * 16) * 2 + cadd;
                ldsm4t(b, bu_base + (uint32_t)krow * 144 + co);
                mma16816(dU + nt2 * 8,     A, b);
                mma16816(dU + nt2 * 8 + 4, A, b + 2);
                ldsm4t(b, bv_base + (uint32_t)krow * 144 + co);
                mma16816(dV + nt2 * 8,     C, b);
                mma16816(dV + nt2 * 8 + 4, C, b + 2);
            }
            {   // 9th n-tile (denominator column 64)
                uint32_t b[2];
                const uint32_t a8 = (uint32_t)(kk * 16 + (l & 15)) * 144 + 128;
                ldsm2t(b, bu_base + a8);
                mma16816(dU + 32, A, b);
                ldsm2t(b, bv_base + a8);
                mma16816(dV + 32, C, b);
            }
        }
        __syncthreads();
    }

    // epilogue: combine chains with r, write partials (col64 = denominator)
    const float rA = g_r[rowA], rB = g_r[rowB];
    float* baseA = g_pnum + ((size_t)js * NV + rowA) * NP;
    float* baseB = g_pnum + ((size_t)js * NV + rowB) * NP;
#pragma unroll
    for (int nt = 0; nt < 9; nt++) {
        float2 oA, oB;
        oA.x = dU[nt * 4 + 0] + rA * dV[nt * 4 + 0];
        oA.y = dU[nt * 4 + 1] + rA * dV[nt * 4 + 1];
        oB.x = dU[nt * 4 + 2] + rB * dV[nt * 4 + 2];
        oB.y = dU[nt * 4 + 3] + rB * dV[nt * 4 + 3];
        const int col = nt * 8 + l2;
        *(float2*)(baseA + col) = oA;
        *(float2*)(baseB + col) = oB;
    }
}

// ---------------------------------------------------------------------------
// Kernel 4: combine j-splits, divide, elu
// ---------------------------------------------------------------------------
__global__ void __launch_bounds__(256) k_final(float* __restrict__ out) {
    const int idx = blockIdx.x * 256 + threadIdx.x;   // 8192*64 threads
    const int row = idx >> 6, f = idx & 63;
    float num = 0.f, den = 0.f;
#pragma unroll
    for (int js = 0; js < JSPL; js++) {
        const float* p = g_pnum + ((size_t)js * NV + row) * NP;
        num += p[f];
        den += p[64];
    }
    const float v = num / den;
    out[(size_t)row * FOUT + f] = v > 0.f ? v : expm1f(v);
}

// ---------------------------------------------------------------------------
extern "C" void kernel_launch(void* const* d_in, const int* in_sizes, int n_in,
                              void* d_out, int out_size) {
    const float* x   = (const float*)d_in[0];
    const int*   adj = (const int*)d_in[1];
    const float* W   = (const float*)d_in[2];
    const float* a   = (const float*)d_in[3];
    float* out = (float*)d_out;

    cudaFuncSetAttribute(k_main, cudaFuncAttributeMaxDynamicSharedMemorySize, SM_MAIN);

    k_wh<<<NV / 16, 256>>>(x, W);
    k_prep<<<NV / 128, 128>>>(a);
    k_main<<<256, 256, SM_MAIN>>>(adj);
    k_final<<<NV * FOUT / 256, 256>>>(out);
}

// round 7
// speedup vs baseline: 7.9715x; 1.1277x over previous
#include <cuda_runtime.h>
#include <cuda_fp16.h>
#include <math.h>
#include <stdint.h>

#define NV    8192
#define FOUT  64
#define NP    72          // padded N: 64 feats + col64 = denominator + pad
#define JSPL  4
#define JW    (NV / JSPL) // 2048 j per CTA
#define CJ    128         // j chunk staged in smem
#define NCH   (JW / CJ)   // 16 chunks

// ------------------------- device scratch (no allocs) -----------------------
__device__ __align__(128) float  g_Wh[NV * FOUT];
__device__ __align__(128) __half g_U[NV * NP];     // [j][72]: B1*Wh, col64=B1
__device__ __align__(128) __half g_V[NV * NP];     // [j][72]: B2*Wh, col64=B2
__device__ __align__(128) __half g_w1h[NV];        // fp16(-Wh1[i])  (threshold)
__device__ __align__(128) __half g_w2h[NV];        // fp16(Wh2[j])
__device__ __align__(128) __half g_rh[NV];         // fp16(exp(-0.8*Wh1[i]))
__device__ __align__(128) float  g_pnum[JSPL * NV * NP];  // partials (col64=den)

// ------------------------- small PTX helpers --------------------------------
__device__ __forceinline__ uint32_t smem_u32(const void* p) {
    uint32_t a;
    asm("{ .reg .u64 t; cvta.to.shared.u64 t, %1; cvt.u32.u64 %0, t; }" : "=r"(a) : "l"(p));
    return a;
}
__device__ __forceinline__ void cpa16(uint32_t dst, const void* src) {
    asm volatile("cp.async.cg.shared.global [%0], [%1], 16;" :: "r"(dst), "l"(src));
}
#define CP_COMMIT() asm volatile("cp.async.commit_group;")
#define CP_WAIT0()  asm volatile("cp.async.wait_group 0;")

__device__ __forceinline__ void ldsm4t(uint32_t* r, uint32_t addr) {
    asm volatile("ldmatrix.sync.aligned.m8n8.x4.trans.shared.b16 {%0,%1,%2,%3}, [%4];"
                 : "=r"(r[0]), "=r"(r[1]), "=r"(r[2]), "=r"(r[3]) : "r"(addr));
}
__device__ __forceinline__ void ldsm2t(uint32_t* r, uint32_t addr) {
    asm volatile("ldmatrix.sync.aligned.m8n8.x2.trans.shared.b16 {%0,%1}, [%2];"
                 : "=r"(r[0]), "=r"(r[1]) : "r"(addr));
}
__device__ __forceinline__ void mma16816(float* d, const uint32_t* a, const uint32_t* b) {
    asm volatile("mma.sync.aligned.m16n8k16.row.col.f32.f16.f16.f32 "
                 "{%0,%1,%2,%3}, {%4,%5,%6,%7}, {%8,%9}, {%0,%1,%2,%3};"
                 : "+f"(d[0]), "+f"(d[1]), "+f"(d[2]), "+f"(d[3])
                 : "r"(a[0]), "r"(a[1]), "r"(a[2]), "r"(a[3]), "r"(b[0]), "r"(b[1]));
}
__device__ __forceinline__ uint32_t hgt2_mask(uint32_t w2, uint32_t th) {
    __half2 a = *(__half2*)&w2, b = *(__half2*)&th;
    __half2 s = __hgt2(a, b);              // 1.0 / 0.0 per half  (0x3C00 codes)
    return *(uint32_t*)&s;
}
__device__ __forceinline__ uint32_t hmul2_u(uint32_t a, uint32_t b) {
    __half2 r = __hmul2(*(__half2*)&a, *(__half2*)&b);
    return *(uint32_t*)&r;
}

// ---------------------------------------------------------------------------
// Kernel 1: Wh = x @ W^T   (fp32, 4x4 register tile over k-major smem)
// block 256 = 16x16 threads; 64 rows x 64 cols per block; grid 128
// ---------------------------------------------------------------------------
#define KP 68   // k-major smem pitch
#define SM_WH (2 * 128 * KP * 4)
__global__ void __launch_bounds__(256) k_wh(const float* __restrict__ x,
                                            const float* __restrict__ W) {
    extern __shared__ float swh[];
    float* xt = swh;             // [k][row]  128 x 68
    float* wt = swh + 128 * KP;  // [k][col]  128 x 68
    const int t = threadIdx.x;
    const int row0 = blockIdx.x * 64;

    for (int i4 = t; i4 < 2048; i4 += 256) {       // x: 64 rows x 128 k
        const int row = i4 >> 5, k4 = (i4 & 31) * 4;
        float4 v = ((const float4*)(x + (size_t)row0 * 128))[i4];
        xt[(k4 + 0) * KP + row] = v.x;
        xt[(k4 + 1) * KP + row] = v.y;
        xt[(k4 + 2) * KP + row] = v.z;
        xt[(k4 + 3) * KP + row] = v.w;
    }
    for (int i4 = t; i4 < 2048; i4 += 256) {       // W: 64 cols x 128 k
        const int col = i4 >> 5, k4 = (i4 & 31) * 4;
        float4 v = ((const float4*)W)[i4];
        wt[(k4 + 0) * KP + col] = v.x;
        wt[(k4 + 1) * KP + col] = v.y;
        wt[(k4 + 2) * KP + col] = v.z;
        wt[(k4 + 3) * KP + col] = v.w;
    }
    __syncthreads();

    const int ty = t >> 4, tx = t & 15;
    float acc[4][4];
#pragma unroll
    for (int i = 0; i < 4; i++)
#pragma unroll
        for (int j = 0; j < 4; j++) acc[i][j] = 0.f;

#pragma unroll 4
    for (int k = 0; k < 128; k++) {
        const float4 xv = *(const float4*)&xt[k * KP + ty * 4];
        const float4 wv = *(const float4*)&wt[k * KP + tx * 4];
        const float xs[4] = {xv.x, xv.y, xv.z, xv.w};
        const float ws[4] = {wv.x, wv.y, wv.z, wv.w};
#pragma unroll
        for (int i = 0; i < 4; i++)
#pragma unroll
            for (int j = 0; j < 4; j++)
                acc[i][j] = fmaf(xs[i], ws[j], acc[i][j]);
    }
#pragma unroll
    for (int i = 0; i < 4; i++)
        *(float4*)(g_Wh + (size_t)(row0 + ty * 4 + i) * FOUT + tx * 4) =
            make_float4(acc[i][0], acc[i][1], acc[i][2], acc[i][3]);
}

// ---------------------------------------------------------------------------
// Kernel 2: per-index scalars + U/V fp16 tables [j][72]
// ---------------------------------------------------------------------------
__global__ void __launch_bounds__(128) k_prep(const float* __restrict__ a) {
    __shared__ float a_s[128];
    const int t = threadIdx.x;
    if (t < 128) a_s[t] = a[t];
    __syncthreads();

    const int j = blockIdx.x * 128 + t;
    float wh[64];
    float s1 = 0.f, s2 = 0.f;
#pragma unroll
    for (int f4 = 0; f4 < 16; f4++) {
        float4 v = ((const float4*)(g_Wh + (size_t)j * FOUT))[f4];
        wh[f4 * 4 + 0] = v.x; wh[f4 * 4 + 1] = v.y;
        wh[f4 * 4 + 2] = v.z; wh[f4 * 4 + 3] = v.w;
        s1 = fmaf(v.x, a_s[f4 * 4 + 0], s1); s2 = fmaf(v.x, a_s[64 + f4 * 4 + 0], s2);
        s1 = fmaf(v.y, a_s[f4 * 4 + 1], s1); s2 = fmaf(v.y, a_s[64 + f4 * 4 + 1], s2);
        s1 = fmaf(v.z, a_s[f4 * 4 + 2], s1); s2 = fmaf(v.z, a_s[64 + f4 * 4 + 2], s2);
        s1 = fmaf(v.w, a_s[f4 * 4 + 3], s1); s2 = fmaf(v.w, a_s[64 + f4 * 4 + 3], s2);
    }
    const float B1 = expf(s2), B2 = expf(0.2f * s2);
    g_w1h[j] = __float2half(-s1);
    g_w2h[j] = __float2half(s2);
    g_rh[j]  = __float2half(expf(-0.8f * s1));

    __half2* U = (__half2*)(g_U + (size_t)j * NP);
    __half2* V = (__half2*)(g_V + (size_t)j * NP);
#pragma unroll
    for (int f2 = 0; f2 < 32; f2++) {
        U[f2] = __floats2half2_rn(B1 * wh[f2 * 2], B1 * wh[f2 * 2 + 1]);
        V[f2] = __floats2half2_rn(B2 * wh[f2 * 2], B2 * wh[f2 * 2 + 1]);
    }
    U[32] = __floats2half2_rn(B1, 0.f);
    V[32] = __floats2half2_rn(B2, 0.f);
#pragma unroll
    for (int f2 = 33; f2 < 36; f2++) { U[f2] = __floats2half2_rn(0.f, 0.f); V[f2] = __floats2half2_rn(0.f, 0.f); }
}

// ---------------------------------------------------------------------------
// Kernel 3: main — single combined MMA chain (r folded into C-operand)
// grid = 256 (64 row-blocks x 4 j-splits), 256 threads (8 warps x 16 rows)
// ---------------------------------------------------------------------------
#define SM_U   0
#define SM_V   36864
#define SM_W2  73728
#define SM_MAIN 74240

__global__ void __launch_bounds__(256, 2) k_main(const int* __restrict__ adj) {
    extern __shared__ char sm[];
    const uint32_t smb = smem_u32(sm);
    const int t = threadIdx.x;
    const int w = t >> 5, l = t & 31;
    const int rb = blockIdx.x >> 2;          // row-block 0..63
    const int js = blockIdx.x & 3;           // j-split 0..3
    const int rt0 = rb * 128;
    const int jb0 = js * JW;

    const int l2 = (l & 3) * 2;
    const int rowA = rt0 + w * 16 + (l >> 2);
    const int rowB = rowA + 8;
    const int* pa0 = adj + (size_t)rowA * NV + jb0 + l2;
    const int* pa1 = adj + (size_t)rowB * NV + jb0 + l2;

    // thresholds + r factors (broadcast half2)
    const uint16_t t0 = *(const uint16_t*)&g_w1h[rowA];
    const uint16_t t1 = *(const uint16_t*)&g_w1h[rowB];
    const uint32_t th0 = (uint32_t)t0 | ((uint32_t)t0 << 16);
    const uint32_t th1 = (uint32_t)t1 | ((uint32_t)t1 << 16);
    const uint16_t r0 = *(const uint16_t*)&g_rh[rowA];
    const uint16_t r1 = *(const uint16_t*)&g_rh[rowB];
    const uint32_t rA2 = (uint32_t)r0 | ((uint32_t)r0 << 16);
    const uint32_t rB2 = (uint32_t)r1 | ((uint32_t)r1 << 16);

    float acc[36];
#pragma unroll
    for (int i = 0; i < 36; i++) acc[i] = 0.f;

    // ---- staging: chunk jc (global j), into buffer buf ----
    auto stage = [&](int buf, int jc) {
#pragma unroll
        for (int i = 0; i < 9; i++) {
            const int idx = t + i * 256;             // 0..2303
            const int hs = idx >= 1152;              // 0:U  1:V
            const int line = idx - hs * 1152;
            const int row = line / 9, seg = line - row * 9;
            const uint32_t dst = smb + (hs ? SM_V : SM_U) + buf * 18432 + row * 144 + seg * 16;
            const char* src = (const char*)(hs ? g_V : g_U) + (size_t)(jc + row) * 144 + seg * 16;
            cpa16(dst, src);
        }
        if (t < 16)
            cpa16(smb + SM_W2 + buf * 256 + t * 16, (const char*)g_w2h + (size_t)jc * 2 + t * 16);
        CP_COMMIT();
    };

    stage(0, jb0);

    for (int c = 0; c < NCH; c++) {
        const int buf = c & 1;
        CP_WAIT0();
        __syncthreads();
        if (c + 1 < NCH) stage((c + 1) & 1, jb0 + (c + 1) * CJ);

        const uint32_t bu_base = smb + SM_U + buf * 18432;
        const uint32_t bv_base = smb + SM_V + buf * 18432;
        const int w2o = SM_W2 + buf * 256;
        const int coff = c * CJ;

#pragma unroll
        for (int kk = 0; kk < 8; kk++) {
            const int jo = coff + kk * 16;
            int2 mA0 = __ldcs((const int2*)(pa0 + jo));
            int2 mA1 = __ldcs((const int2*)(pa0 + jo + 8));
            int2 mB0 = __ldcs((const int2*)(pa1 + jo));
            int2 mB1 = __ldcs((const int2*)(pa1 + jo + 8));

            const uint32_t w2lo = *(const uint32_t*)(sm + w2o + (kk * 16 + l2) * 2);
            const uint32_t w2hi = *(const uint32_t*)(sm + w2o + (kk * 16 + l2 + 8) * 2);

            const uint32_t MA0 = (uint32_t)mA0.x * 0x3C00u + (uint32_t)mA0.y * 0x3C000000u;
            const uint32_t MA1 = (uint32_t)mA1.x * 0x3C00u + (uint32_t)mA1.y * 0x3C000000u;
            const uint32_t MB0 = (uint32_t)mB0.x * 0x3C00u + (uint32_t)mB0.y * 0x3C000000u;
            const uint32_t MB1 = (uint32_t)mB1.x * 0x3C00u + (uint32_t)mB1.y * 0x3C000000u;

            uint32_t A[4], C[4];
            A[0] = MA0 & hgt2_mask(w2lo, th0);
            A[1] = MB0 & hgt2_mask(w2lo, th1);
            A[2] = MA1 & hgt2_mask(w2hi, th0);
            A[3] = MB1 & hgt2_mask(w2hi, th1);
            C[0] = hmul2_u(A[0] ^ MA0, rA2);
            C[1] = hmul2_u(A[1] ^ MB0, rB2);
            C[2] = hmul2_u(A[2] ^ MA1, rA2);
            C[3] = hmul2_u(A[3] ^ MB1, rB2);

            const int krow = kk * 16 + ((l >> 3) & 1) * 8 + (l & 7);
            const uint32_t cadd = (uint32_t)((l >> 4) * 8) * 2;

#pragma unroll
            for (int nt2 = 0; nt2 < 4; nt2++) {
                uint32_t b[4];
                const uint32_t co = (uint32_t)(nt2 * 16) * 2 + cadd;
                ldsm4t(b, bu_base + (uint32_t)krow * 144 + co);
                mma16816(acc + nt2 * 8,     A, b);
                mma16816(acc + nt2 * 8 + 4, A, b + 2);
                ldsm4t(b, bv_base + (uint32_t)krow * 144 + co);
                mma16816(acc + nt2 * 8,     C, b);
                mma16816(acc + nt2 * 8 + 4, C, b + 2);
            }
            {   // 9th n-tile (denominator column 64)
                uint32_t b[2];
                const uint32_t a8 = (uint32_t)(kk * 16 + (l & 15)) * 144 + 128;
                ldsm2t(b, bu_base + a8);
                mma16816(acc + 32, A, b);
                ldsm2t(b, bv_base + a8);
                mma16816(acc + 32, C, b);
            }
        }
        __syncthreads();
    }

    // epilogue: write partials (col64 = denominator, r already applied)
    float* baseA = g_pnum + ((size_t)js * NV + rowA) * NP;
    float* baseB = g_pnum + ((size_t)js * NV + rowB) * NP;
#pragma unroll
    for (int nt = 0; nt < 9; nt++) {
        const int col = nt * 8 + l2;
        *(float2*)(baseA + col) = make_float2(acc[nt * 4 + 0], acc[nt * 4 + 1]);
        *(float2*)(baseB + col) = make_float2(acc[nt * 4 + 2], acc[nt * 4 + 3]);
    }
}

// ---------------------------------------------------------------------------
// Kernel 4: combine j-splits, divide, elu  (float4 vectorized)
// ---------------------------------------------------------------------------
__global__ void __launch_bounds__(256) k_final(float* __restrict__ out) {
    const int idx = blockIdx.x * 256 + threadIdx.x;   // 8192*16 slots
    const int row = idx >> 4, f4 = idx & 15;
    float4 num = make_float4(0.f, 0.f, 0.f, 0.f);
    float den = 0.f;
#pragma unroll
    for (int js = 0; js < JSPL; js++) {
        const float* p = g_pnum + ((size_t)js * NV + row) * NP;
        const float4 v = *(const float4*)(p + f4 * 4);
        num.x += v.x; num.y += v.y; num.z += v.z; num.w += v.w;
        den += p[64];
    }
    const float inv = 1.0f / den;
    float4 o;
    float a0 = num.x * inv; o.x = a0 > 0.f ? a0 : expm1f(a0);
    float a1 = num.y * inv; o.y = a1 > 0.f ? a1 : expm1f(a1);
    float a2 = num.z * inv; o.z = a2 > 0.f ? a2 : expm1f(a2);
    float a3 = num.w * inv; o.w = a3 > 0.f ? a3 : expm1f(a3);
    *(float4*)(out + (size_t)row * FOUT + f4 * 4) = o;
}

// ---------------------------------------------------------------------------
extern "C" void kernel_launch(void* const* d_in, const int* in_sizes, int n_in,
                              void* d_out, int out_size) {
    const float* x   = (const float*)d_in[0];
    const int*   adj = (const int*)d_in[1];
    const float* W   = (const float*)d_in[2];
    const float* a   = (const float*)d_in[3];
    float* out = (float*)d_out;

    cudaFuncSetAttribute(k_wh,   cudaFuncAttributeMaxDynamicSharedMemorySize, SM_WH);
    cudaFuncSetAttribute(k_main, cudaFuncAttributeMaxDynamicSharedMemorySize, SM_MAIN);

    k_wh<<<NV / 64, 256, SM_WH>>>(x, W);
    k_prep<<<NV / 128, 128>>>(a);
    k_main<<<256, 256, SM_MAIN>>>(adj);
    k_final<<<NV * 16 / 256, 256>>>(out);
}

// round 8
// speedup vs baseline: 9.1753x; 1.1510x over previous
#include <cuda_runtime.h>
#include <cuda_fp16.h>
#include <math.h>
#include <stdint.h>

#define NV    8192
#define FOUT  64
#define NP    72          // padded N: 64 feats + col64 = denominator + pad
#define JSPL  4
#define JW    (NV / JSPL) // 2048 j per CTA
#define CJ    128         // j chunk staged in smem
#define NCH   (JW / CJ)   // 16 chunks

// ------------------------- device scratch (no allocs) -----------------------
__device__ __align__(128) float  g_Wh[NV * FOUT];
__device__ __align__(128) __half g_WhH[NV * NP];   // [j][72]: fp16 Wh, col64=1
__device__ __align__(128) __half g_w1h[NV];        // fp16(-Wh1[i])  (threshold)
__device__ __align__(128) __half g_w2h[NV];        // fp16(Wh2[j])
__device__ __align__(128) __half g_b1h[NV];        // fp16(exp(Wh2[j]))
__device__ __align__(128) __half g_b2h[NV];        // fp16(exp(0.2*Wh2[j]))
__device__ __align__(128) __half g_rh[NV];         // fp16(exp(-0.8*Wh1[i]))
__device__ __align__(128) float  g_pnum[JSPL * NV * NP];  // partials (col64=den)

// ------------------------- small PTX helpers --------------------------------
__device__ __forceinline__ uint32_t smem_u32(const void* p) {
    uint32_t a;
    asm("{ .reg .u64 t; cvta.to.shared.u64 t, %1; cvt.u32.u64 %0, t; }" : "=r"(a) : "l"(p));
    return a;
}
__device__ __forceinline__ void cpa16(uint32_t dst, const void* src) {
    asm volatile("cp.async.cg.shared.global [%0], [%1], 16;" :: "r"(dst), "l"(src));
}
#define CP_COMMIT() asm volatile("cp.async.commit_group;")
#define CP_WAIT0()  asm volatile("cp.async.wait_group 0;")

__device__ __forceinline__ void ldsm4t(uint32_t* r, uint32_t addr) {
    asm volatile("ldmatrix.sync.aligned.m8n8.x4.trans.shared.b16 {%0,%1,%2,%3}, [%4];"
                 : "=r"(r[0]), "=r"(r[1]), "=r"(r[2]), "=r"(r[3]) : "r"(addr));
}
__device__ __forceinline__ void ldsm2t(uint32_t* r, uint32_t addr) {
    asm volatile("ldmatrix.sync.aligned.m8n8.x2.trans.shared.b16 {%0,%1}, [%2];"
                 : "=r"(r[0]), "=r"(r[1]) : "r"(addr));
}
__device__ __forceinline__ void mma16816(float* d, const uint32_t* a, const uint32_t* b) {
    asm volatile("mma.sync.aligned.m16n8k16.row.col.f32.f16.f16.f32 "
                 "{%0,%1,%2,%3}, {%4,%5,%6,%7}, {%8,%9}, {%0,%1,%2,%3};"
                 : "+f"(d[0]), "+f"(d[1]), "+f"(d[2]), "+f"(d[3])
                 : "r"(a[0]), "r"(a[1]), "r"(a[2]), "r"(a[3]), "r"(b[0]), "r"(b[1]));
}
__device__ __forceinline__ uint32_t hgt2_mask(uint32_t w2, uint32_t th) {
    __half2 a = *(__half2*)&w2, b = *(__half2*)&th;
    __half2 s = __hgt2(a, b);              // 1.0 / 0.0 per half  (0x3C00 codes)
    return *(uint32_t*)&s;
}
__device__ __forceinline__ uint32_t hmul2_u(uint32_t a, uint32_t b) {
    __half2 r = __hmul2(*(__half2*)&a, *(__half2*)&b);
    return *(uint32_t*)&r;
}
__device__ __forceinline__ uint32_t hfma2_u(uint32_t a, uint32_t b, uint32_t c) {
    __half2 r = __hfma2(*(__half2*)&a, *(__half2*)&b, *(__half2*)&c);
    return *(uint32_t*)&r;
}

// ---------------------------------------------------------------------------
// Kernel 1: Wh = x @ W^T   (fp32, 4x4 register tile over k-major smem)
// ---------------------------------------------------------------------------
#define KP 68   // k-major smem pitch
#define SM_WHK (2 * 128 * KP * 4)
__global__ void __launch_bounds__(256) k_wh(const float* __restrict__ x,
                                            const float* __restrict__ W) {
    extern __shared__ float swh[];
    float* xt = swh;             // [k][row]  128 x 68
    float* wt = swh + 128 * KP;  // [k][col]  128 x 68
    const int t = threadIdx.x;
    const int row0 = blockIdx.x * 64;

    for (int i4 = t; i4 < 2048; i4 += 256) {       // x: 64 rows x 128 k
        const int row = i4 >> 5, k4 = (i4 & 31) * 4;
        float4 v = ((const float4*)(x + (size_t)row0 * 128))[i4];
        xt[(k4 + 0) * KP + row] = v.x;
        xt[(k4 + 1) * KP + row] = v.y;
        xt[(k4 + 2) * KP + row] = v.z;
        xt[(k4 + 3) * KP + row] = v.w;
    }
    for (int i4 = t; i4 < 2048; i4 += 256) {       // W: 64 cols x 128 k
        const int col = i4 >> 5, k4 = (i4 & 31) * 4;
        float4 v = ((const float4*)W)[i4];
        wt[(k4 + 0) * KP + col] = v.x;
        wt[(k4 + 1) * KP + col] = v.y;
        wt[(k4 + 2) * KP + col] = v.z;
        wt[(k4 + 3) * KP + col] = v.w;
    }
    __syncthreads();

    const int ty = t >> 4, tx = t & 15;
    float acc[4][4];
#pragma unroll
    for (int i = 0; i < 4; i++)
#pragma unroll
        for (int j = 0; j < 4; j++) acc[i][j] = 0.f;

#pragma unroll 4
    for (int k = 0; k < 128; k++) {
        const float4 xv = *(const float4*)&xt[k * KP + ty * 4];
        const float4 wv = *(const float4*)&wt[k * KP + tx * 4];
        const float xs[4] = {xv.x, xv.y, xv.z, xv.w};
        const float ws[4] = {wv.x, wv.y, wv.z, wv.w};
#pragma unroll
        for (int i = 0; i < 4; i++)
#pragma unroll
            for (int j = 0; j < 4; j++)
                acc[i][j] = fmaf(xs[i], ws[j], acc[i][j]);
    }
#pragma unroll
    for (int i = 0; i < 4; i++)
        *(float4*)(g_Wh + (size_t)(row0 + ty * 4 + i) * FOUT + tx * 4) =
            make_float4(acc[i][0], acc[i][1], acc[i][2], acc[i][3]);
}

// ---------------------------------------------------------------------------
// Kernel 2: per-index scalars + fp16 Wh table [j][72] (col64 = 1)
// ---------------------------------------------------------------------------
__global__ void __launch_bounds__(128) k_prep(const float* __restrict__ a) {
    __shared__ float a_s[128];
    const int t = threadIdx.x;
    if (t < 128) a_s[t] = a[t];
    __syncthreads();

    const int j = blockIdx.x * 128 + t;
    float wh[64];
    float s1 = 0.f, s2 = 0.f;
#pragma unroll
    for (int f4 = 0; f4 < 16; f4++) {
        float4 v = ((const float4*)(g_Wh + (size_t)j * FOUT))[f4];
        wh[f4 * 4 + 0] = v.x; wh[f4 * 4 + 1] = v.y;
        wh[f4 * 4 + 2] = v.z; wh[f4 * 4 + 3] = v.w;
        s1 = fmaf(v.x, a_s[f4 * 4 + 0], s1); s2 = fmaf(v.x, a_s[64 + f4 * 4 + 0], s2);
        s1 = fmaf(v.y, a_s[f4 * 4 + 1], s1); s2 = fmaf(v.y, a_s[64 + f4 * 4 + 1], s2);
        s1 = fmaf(v.z, a_s[f4 * 4 + 2], s1); s2 = fmaf(v.z, a_s[64 + f4 * 4 + 2], s2);
        s1 = fmaf(v.w, a_s[f4 * 4 + 3], s1); s2 = fmaf(v.w, a_s[64 + f4 * 4 + 3], s2);
    }
    g_w1h[j] = __float2half(-s1);
    g_w2h[j] = __float2half(s2);
    g_b1h[j] = __float2half(expf(s2));
    g_b2h[j] = __float2half(expf(0.2f * s2));
    g_rh[j]  = __float2half(expf(-0.8f * s1));

    __half2* H = (__half2*)(g_WhH + (size_t)j * NP);
#pragma unroll
    for (int f2 = 0; f2 < 32; f2++)
        H[f2] = __floats2half2_rn(wh[f2 * 2], wh[f2 * 2 + 1]);
    H[32] = __floats2half2_rn(1.0f, 0.f);
#pragma unroll
    for (int f2 = 33; f2 < 36; f2++) H[f2] = __floats2half2_rn(0.f, 0.f);
}

// ---------------------------------------------------------------------------
// Kernel 3: main — fp16 weight built in registers, SINGLE MMA chain
// grid = 256 (64 row-blocks x 4 j-splits), 256 threads (8 warps x 16 rows)
// ---------------------------------------------------------------------------
#define SM_WH   0                       // 2 x 18432
#define SM_W2   36864                   // 2 x 256
#define SM_B1   37376                   // 2 x 256
#define SM_B2   37888                   // 2 x 256
#define SM_MAIN 38400

__global__ void __launch_bounds__(256, 2) k_main(const int* __restrict__ adj) {
    extern __shared__ char sm[];
    const uint32_t smb = smem_u32(sm);
    const int t = threadIdx.x;
    const int w = t >> 5, l = t & 31;
    const int rb = blockIdx.x >> 2;          // row-block 0..63
    const int js = blockIdx.x & 3;           // j-split 0..3
    const int rt0 = rb * 128;
    const int jb0 = js * JW;

    const int l2 = (l & 3) * 2;
    const int rowA = rt0 + w * 16 + (l >> 2);
    const int rowB = rowA + 8;
    const int* pa0 = adj + (size_t)rowA * NV + jb0 + l2;
    const int* pa1 = adj + (size_t)rowB * NV + jb0 + l2;

    // thresholds + r factors (broadcast half2)
    const uint16_t t0 = *(const uint16_t*)&g_w1h[rowA];
    const uint16_t t1 = *(const uint16_t*)&g_w1h[rowB];
    const uint32_t th0 = (uint32_t)t0 | ((uint32_t)t0 << 16);
    const uint32_t th1 = (uint32_t)t1 | ((uint32_t)t1 << 16);
    const uint16_t r0 = *(const uint16_t*)&g_rh[rowA];
    const uint16_t r1 = *(const uint16_t*)&g_rh[rowB];
    const uint32_t rA2 = (uint32_t)r0 | ((uint32_t)r0 << 16);
    const uint32_t rB2 = (uint32_t)r1 | ((uint32_t)r1 << 16);

    float acc[36];
#pragma unroll
    for (int i = 0; i < 36; i++) acc[i] = 0.f;

    // ---- staging: chunk jc (global j), into buffer buf ----
    auto stage = [&](int buf, int jc) {
#pragma unroll
        for (int i = 0; i < 4; i++) {
            const int idx = t + i * 256;             // 0..1023
            const int row = idx / 9, seg = idx - row * 9;
            cpa16(smb + SM_WH + buf * 18432 + row * 144 + seg * 16,
                  (const char*)g_WhH + (size_t)(jc + row) * 144 + seg * 16);
        }
        if (t < 128) {
            const int idx = 1024 + t;                // 1024..1151
            const int row = idx / 9, seg = idx - row * 9;
            cpa16(smb + SM_WH + buf * 18432 + row * 144 + seg * 16,
                  (const char*)g_WhH + (size_t)(jc + row) * 144 + seg * 16);
        }
        if (t < 16)
            cpa16(smb + SM_W2 + buf * 256 + t * 16, (const char*)g_w2h + (size_t)jc * 2 + t * 16);
        else if (t < 32)
            cpa16(smb + SM_B1 + buf * 256 + (t - 16) * 16, (const char*)g_b1h + (size_t)jc * 2 + (t - 16) * 16);
        else if (t < 48)
            cpa16(smb + SM_B2 + buf * 256 + (t - 32) * 16, (const char*)g_b2h + (size_t)jc * 2 + (t - 32) * 16);
        CP_COMMIT();
    };

    stage(0, jb0);

    for (int c = 0; c < NCH; c++) {
        const int buf = c & 1;
        CP_WAIT0();
        __syncthreads();
        if (c + 1 < NCH) stage((c + 1) & 1, jb0 + (c + 1) * CJ);

        const uint32_t bw_base = smb + SM_WH + buf * 18432;
        const int w2o = SM_W2 + buf * 256;
        const int b1o = SM_B1 + buf * 256;
        const int b2o = SM_B2 + buf * 256;
        const int coff = c * CJ;

#pragma unroll
        for (int kk = 0; kk < 8; kk++) {
            const int jo = coff + kk * 16;
            int2 mA0 = __ldcs((const int2*)(pa0 + jo));
            int2 mA1 = __ldcs((const int2*)(pa0 + jo + 8));
            int2 mB0 = __ldcs((const int2*)(pa1 + jo));
            int2 mB1 = __ldcs((const int2*)(pa1 + jo + 8));

            const int klo = (kk * 16 + l2) * 2, khi = (kk * 16 + l2 + 8) * 2;
            const uint32_t w2lo = *(const uint32_t*)(sm + w2o + klo);
            const uint32_t w2hi = *(const uint32_t*)(sm + w2o + khi);
            const uint32_t b1lo = *(const uint32_t*)(sm + b1o + klo);
            const uint32_t b1hi = *(const uint32_t*)(sm + b1o + khi);
            const uint32_t b2lo = *(const uint32_t*)(sm + b2o + klo);
            const uint32_t b2hi = *(const uint32_t*)(sm + b2o + khi);

            const uint32_t MA0 = (uint32_t)mA0.x * 0x3C00u + (uint32_t)mA0.y * 0x3C000000u;
            const uint32_t MA1 = (uint32_t)mA1.x * 0x3C00u + (uint32_t)mA1.y * 0x3C000000u;
            const uint32_t MB0 = (uint32_t)mB0.x * 0x3C00u + (uint32_t)mB0.y * 0x3C000000u;
            const uint32_t MB1 = (uint32_t)mB1.x * 0x3C00u + (uint32_t)mB1.y * 0x3C000000u;

            // rb2 per row/k-half (r * b2, one rounding)
            const uint32_t rb2loA = hmul2_u(b2lo, rA2), rb2hiA = hmul2_u(b2hi, rA2);
            const uint32_t rb2loB = hmul2_u(b2lo, rB2), rb2hiB = hmul2_u(b2hi, rB2);

            uint32_t A0 = MA0 & hgt2_mask(w2lo, th0);
            uint32_t A1 = MB0 & hgt2_mask(w2lo, th1);
            uint32_t A2 = MA1 & hgt2_mask(w2hi, th0);
            uint32_t A3 = MB1 & hgt2_mask(w2hi, th1);

            uint32_t Q[4];
            Q[0] = hfma2_u(A0 ^ MA0, rb2loA, hmul2_u(A0, b1lo));
            Q[1] = hfma2_u(A1 ^ MB0, rb2loB, hmul2_u(A1, b1lo));
            Q[2] = hfma2_u(A2 ^ MA1, rb2hiA, hmul2_u(A2, b1hi));
            Q[3] = hfma2_u(A3 ^ MB1, rb2hiB, hmul2_u(A3, b1hi));

            const int krow = kk * 16 + ((l >> 3) & 1) * 8 + (l & 7);
            const uint32_t cadd = (uint32_t)((l >> 4) * 8) * 2;

#pragma unroll
            for (int nt2 = 0; nt2 < 4; nt2++) {
                uint32_t b[4];
                const uint32_t co = (uint32_t)(nt2 * 16) * 2 + cadd;
                ldsm4t(b, bw_base + (uint32_t)krow * 144 + co);
                mma16816(acc + nt2 * 8,     Q, b);
                mma16816(acc + nt2 * 8 + 4, Q, b + 2);
            }
            {   // 9th n-tile: col64 = 1.0 -> denominator
                uint32_t b[2];
                const uint32_t a8 = (uint32_t)(kk * 16 + (l & 15)) * 144 + 128;
                ldsm2t(b, bw_base + a8);
                mma16816(acc + 32, Q, b);
            }
        }
        __syncthreads();
    }

    // epilogue: write partials (col64 = denominator)
    float* baseA = g_pnum + ((size_t)js * NV + rowA) * NP;
    float* baseB = g_pnum + ((size_t)js * NV + rowB) * NP;
#pragma unroll
    for (int nt = 0; nt < 9; nt++) {
        const int col = nt * 8 + l2;
        *(float2*)(baseA + col) = make_float2(acc[nt * 4 + 0], acc[nt * 4 + 1]);
        *(float2*)(baseB + col) = make_float2(acc[nt * 4 + 2], acc[nt * 4 + 3]);
    }
}

// ---------------------------------------------------------------------------
// Kernel 4: combine j-splits, divide, elu  (float4 vectorized)
// ---------------------------------------------------------------------------
__global__ void __launch_bounds__(256) k_final(float* __restrict__ out) {
    const int idx = blockIdx.x * 256 + threadIdx.x;   // 8192*16 slots
    const int row = idx >> 4, f4 = idx & 15;
    float4 num = make_float4(0.f, 0.f, 0.f, 0.f);
    float den = 0.f;
#pragma unroll
    for (int js = 0; js < JSPL; js++) {
        const float* p = g_pnum + ((size_t)js * NV + row) * NP;
        const float4 v = *(const float4*)(p + f4 * 4);
        num.x += v.x; num.y += v.y; num.z += v.z; num.w += v.w;
        den += p[64];
    }
    const float inv = 1.0f / den;
    float4 o;
    float a0 = num.x * inv; o.x = a0 > 0.f ? a0 : expm1f(a0);
    float a1 = num.y * inv; o.y = a1 > 0.f ? a1 : expm1f(a1);
    float a2 = num.z * inv; o.z = a2 > 0.f ? a2 : expm1f(a2);
    float a3 = num.w * inv; o.w = a3 > 0.f ? a3 : expm1f(a3);
    *(float4*)(out + (size_t)row * FOUT + f4 * 4) = o;
}

// ---------------------------------------------------------------------------
extern "C" void kernel_launch(void* const* d_in, const int* in_sizes, int n_in,
                              void* d_out, int out_size) {
    const float* x   = (const float*)d_in[0];
    const int*   adj = (const int*)d_in[1];
    const float* W   = (const float*)d_in[2];
    const float* a   = (const float*)d_in[3];
    float* out = (float*)d_out;

    cudaFuncSetAttribute(k_wh,   cudaFuncAttributeMaxDynamicSharedMemorySize, SM_WHK);
    cudaFuncSetAttribute(k_main, cudaFuncAttributeMaxDynamicSharedMemorySize, SM_MAIN);

    k_wh<<<NV / 64, 256, SM_WHK>>>(x, W);
    k_prep<<<NV / 128, 128>>>(a);
    k_main<<<256, 256, SM_MAIN>>>(adj);
    k_final<<<NV * 16 / 256, 256>>>(out);
}

// round 11
// speedup vs baseline: 9.3813x; 1.0225x over previous
#include <cuda_runtime.h>
#include <cuda_fp16.h>
#include <math.h>
#include <stdint.h>

#define NV    8192
#define FOUT  64
#define NP    72          // padded N: 64 feats + col64 = denominator + pad
#define JSPL  4
#define JW    (NV / JSPL) // 2048 j per CTA
#define CJ    64          // j chunk staged in smem
#define NCH   (JW / CJ)   // 32 chunks

// ------------------------- device scratch (no allocs) -----------------------
__device__ __align__(128) float  g_Wh[NV * FOUT];
__device__ __align__(128) __half g_WhH[NV * NP];   // [j][72]: fp16 Wh, col64=1
__device__ __align__(128) __half g_w1h[NV];        // fp16(-Wh1[i])  (threshold)
__device__ __align__(128) __half g_w2h[NV];        // fp16(Wh2[j])
__device__ __align__(128) __half g_b1h[NV];        // fp16(exp(Wh2[j]))
__device__ __align__(128) __half g_b2h[NV];        // fp16(exp(0.2*Wh2[j]))
__device__ __align__(128) __half g_rh[NV];         // fp16(exp(-0.8*Wh1[i]))
__device__ __align__(128) float  g_pnum[JSPL * NV * NP];  // partials (col64=den)

// ------------------------- small PTX helpers --------------------------------
__device__ __forceinline__ uint32_t smem_u32(const void* p) {
    uint32_t a;
    asm("{ .reg .u64 t; cvta.to.shared.u64 t, %1; cvt.u32.u64 %0, t; }" : "=r"(a) : "l"(p));
    return a;
}
__device__ __forceinline__ void cpa16(uint32_t dst, const void* src) {
    asm volatile("cp.async.cg.shared.global [%0], [%1], 16;" :: "r"(dst), "l"(src));
}
#define CP_COMMIT() asm volatile("cp.async.commit_group;")
#define CP_WAIT0()  asm volatile("cp.async.wait_group 0;")

__device__ __forceinline__ void ldsm4t(uint32_t* r, uint32_t addr) {
    asm volatile("ldmatrix.sync.aligned.m8n8.x4.trans.shared.b16 {%0,%1,%2,%3}, [%4];"
                 : "=r"(r[0]), "=r"(r[1]), "=r"(r[2]), "=r"(r[3]) : "r"(addr));
}
__device__ __forceinline__ void ldsm2t(uint32_t* r, uint32_t addr) {
    asm volatile("ldmatrix.sync.aligned.m8n8.x2.trans.shared.b16 {%0,%1}, [%2];"
                 : "=r"(r[0]), "=r"(r[1]) : "r"(addr));
}
__device__ __forceinline__ void mma16816(float* d, const uint32_t* a, const uint32_t* b) {
    asm volatile("mma.sync.aligned.m16n8k16.row.col.f32.f16.f16.f32 "
                 "{%0,%1,%2,%3}, {%4,%5,%6,%7}, {%8,%9}, {%0,%1,%2,%3};"
                 : "+f"(d[0]), "+f"(d[1]), "+f"(d[2]), "+f"(d[3])
                 : "r"(a[0]), "r"(a[1]), "r"(a[2]), "r"(a[3]), "r"(b[0]), "r"(b[1]));
}
__device__ __forceinline__ uint32_t hgt2_mask(uint32_t w2, uint32_t th) {
    __half2 a = *(__half2*)&w2, b = *(__half2*)&th;
    __half2 s = __hgt2(a, b);              // 1.0 / 0.0 per half  (0x3C00 codes)
    return *(uint32_t*)&s;
}
__device__ __forceinline__ uint32_t hmul2_u(uint32_t a, uint32_t b) {
    __half2 r = __hmul2(*(__half2*)&a, *(__half2*)&b);
    return *(uint32_t*)&r;
}
__device__ __forceinline__ uint32_t hfma2_u(uint32_t a, uint32_t b, uint32_t c) {
    __half2 r = __hfma2(*(__half2*)&a, *(__half2*)&b, *(__half2*)&c);
    return *(uint32_t*)&r;
}

// ---------------------------------------------------------------------------
// Kernel 1: Wh = x @ W^T   (fp32, 4x4 register tile over k-major smem)
// ---------------------------------------------------------------------------
#define KP 68   // k-major smem pitch
#define SM_WHK (2 * 128 * KP * 4)
__global__ void __launch_bounds__(256) k_wh(const float* __restrict__ x,
                                            const float* __restrict__ W) {
    extern __shared__ float swh[];
    float* xt = swh;             // [k][row]  128 x 68
    float* wt = swh + 128 * KP;  // [k][col]  128 x 68
    const int t = threadIdx.x;
    const int row0 = blockIdx.x * 64;

    for (int i4 = t; i4 < 2048; i4 += 256) {       // x: 64 rows x 128 k
        const int row = i4 >> 5, k4 = (i4 & 31) * 4;
        float4 v = ((const float4*)(x + (size_t)row0 * 128))[i4];
        xt[(k4 + 0) * KP + row] = v.x;
        xt[(k4 + 1) * KP + row] = v.y;
        xt[(k4 + 2) * KP + row] = v.z;
        xt[(k4 + 3) * KP + row] = v.w;
    }
    for (int i4 = t; i4 < 2048; i4 += 256) {       // W: 64 cols x 128 k
        const int col = i4 >> 5, k4 = (i4 & 31) * 4;
        float4 v = ((const float4*)W)[i4];
        wt[(k4 + 0) * KP + col] = v.x;
        wt[(k4 + 1) * KP + col] = v.y;
        wt[(k4 + 2) * KP + col] = v.z;
        wt[(k4 + 3) * KP + col] = v.w;
    }
    __syncthreads();

    const int ty = t >> 4, tx = t & 15;
    float acc[4][4];
#pragma unroll
    for (int i = 0; i < 4; i++)
#pragma unroll
        for (int j = 0; j < 4; j++) acc[i][j] = 0.f;

#pragma unroll 4
    for (int k = 0; k < 128; k++) {
        const float4 xv = *(const float4*)&xt[k * KP + ty * 4];
        const float4 wv = *(const float4*)&wt[k * KP + tx * 4];
        const float xs[4] = {xv.x, xv.y, xv.z, xv.w};
        const float ws[4] = {wv.x, wv.y, wv.z, wv.w};
#pragma unroll
        for (int i = 0; i < 4; i++)
#pragma unroll
            for (int j = 0; j < 4; j++)
                acc[i][j] = fmaf(xs[i], ws[j], acc[i][j]);
    }
#pragma unroll
    for (int i = 0; i < 4; i++)
        *(float4*)(g_Wh + (size_t)(row0 + ty * 4 + i) * FOUT + tx * 4) =
            make_float4(acc[i][0], acc[i][1], acc[i][2], acc[i][3]);
}

// ---------------------------------------------------------------------------
// Kernel 2: per-index scalars + fp16 Wh table [j][72] (col64 = 1)
// ---------------------------------------------------------------------------
__global__ void __launch_bounds__(128) k_prep(const float* __restrict__ a) {
    __shared__ float a_s[128];
    const int t = threadIdx.x;
    if (t < 128) a_s[t] = a[t];
    __syncthreads();

    const int j = blockIdx.x * 128 + t;
    float wh[64];
    float s1 = 0.f, s2 = 0.f;
#pragma unroll
    for (int f4 = 0; f4 < 16; f4++) {
        float4 v = ((const float4*)(g_Wh + (size_t)j * FOUT))[f4];
        wh[f4 * 4 + 0] = v.x; wh[f4 * 4 + 1] = v.y;
        wh[f4 * 4 + 2] = v.z; wh[f4 * 4 + 3] = v.w;
        s1 = fmaf(v.x, a_s[f4 * 4 + 0], s1); s2 = fmaf(v.x, a_s[64 + f4 * 4 + 0], s2);
        s1 = fmaf(v.y, a_s[f4 * 4 + 1], s1); s2 = fmaf(v.y, a_s[64 + f4 * 4 + 1], s2);
        s1 = fmaf(v.z, a_s[f4 * 4 + 2], s1); s2 = fmaf(v.z, a_s[64 + f4 * 4 + 2], s2);
        s1 = fmaf(v.w, a_s[f4 * 4 + 3], s1); s2 = fmaf(v.w, a_s[64 + f4 * 4 + 3], s2);
    }
    g_w1h[j] = __float2half(-s1);
    g_w2h[j] = __float2half(s2);
    g_b1h[j] = __float2half(expf(s2));
    g_b2h[j] = __float2half(expf(0.2f * s2));
    g_rh[j]  = __float2half(expf(-0.8f * s1));

    __half2* H = (__half2*)(g_WhH + (size_t)j * NP);
#pragma unroll
    for (int f2 = 0; f2 < 32; f2++)
        H[f2] = __floats2half2_rn(wh[f2 * 2], wh[f2 * 2 + 1]);
    H[32] = __floats2half2_rn(1.0f, 0.f);
#pragma unroll
    for (int f2 = 33; f2 < 36; f2++) H[f2] = __floats2half2_rn(0.f, 0.f);
}

// ---------------------------------------------------------------------------
// Kernel 3: main — adj staged by cp.async, zero long-latency ops in loop
// grid = 256 (64 row-blocks x 4 j-splits), 256 threads (8 warps x 16 rows)
// smem: adj 2x34816 | WhH 2x9216 | scalars 2x512  = 89088 B
// ---------------------------------------------------------------------------
#define APITCH  272                     // 64 ints (256B) padded -> bank spread
#define SM_ADJ  0                       // 2 x 128*272 = 69632
#define SM_WH   69632                   // 2 x 9216    = 18432
#define SM_SC   88064                   // 2 x 512 (w2 | +128 b1 | +256 b2)
#define SM_MAIN 89088

__global__ void __launch_bounds__(256, 2) k_main(const int* __restrict__ adj) {
    extern __shared__ char sm[];
    const uint32_t smb = smem_u32(sm);
    const int t = threadIdx.x;
    const int w = t >> 5, l = t & 31;
    const int rb = blockIdx.x >> 2;          // row-block 0..63
    const int js = blockIdx.x & 3;           // j-split 0..3
    const int rt0 = rb * 128;
    const int jb0 = js * JW;

    const int l2 = (l & 3) * 2;
    const int rowA = rt0 + w * 16 + (l >> 2);
    const int rowB = rowA + 8;
    const int rlA = w * 16 + (l >> 2);       // local rows
    const int rlB = rlA + 8;

    // thresholds + r factors (broadcast half2)
    const uint16_t t0 = *(const uint16_t*)&g_w1h[rowA];
    const uint16_t t1 = *(const uint16_t*)&g_w1h[rowB];
    const uint32_t th0 = (uint32_t)t0 | ((uint32_t)t0 << 16);
    const uint32_t th1 = (uint32_t)t1 | ((uint32_t)t1 << 16);
    const uint16_t r0 = *(const uint16_t*)&g_rh[rowA];
    const uint16_t r1 = *(const uint16_t*)&g_rh[rowB];
    const uint32_t rA2 = (uint32_t)r0 | ((uint32_t)r0 << 16);
    const uint32_t rB2 = (uint32_t)r1 | ((uint32_t)r1 << 16);

    float acc[36];
#pragma unroll
    for (int i = 0; i < 36; i++) acc[i] = 0.f;

    // ---- staging: chunk at global j = jc, into buffer buf ----
    auto stage = [&](int buf, int jc) {
        const char* asrc = (const char*)(adj + (size_t)rt0 * NV + jc);
        const uint32_t adst = smb + SM_ADJ + buf * 34816;
#pragma unroll
        for (int i = 0; i < 8; i++) {
            const int idx = t + i * 256;             // 0..2047 (128 rows x 16 seg)
            const int row = idx >> 4, seg = idx & 15;
            cpa16(adst + row * APITCH + seg * 16,
                  asrc + (size_t)row * (NV * 4) + seg * 16);
        }
#pragma unroll
        for (int i = 0; i < 2; i++) {
            const int idx = t + i * 256;             // 0..511
            const int row = idx / 9, seg = idx - row * 9;
            cpa16(smb + SM_WH + buf * 9216 + row * 144 + seg * 16,
                  (const char*)g_WhH + (size_t)(jc + row) * 144 + seg * 16);
        }
        if (t < 64) {
            const int idx = 512 + t;                 // 512..575
            const int row = idx / 9, seg = idx - row * 9;
            cpa16(smb + SM_WH + buf * 9216 + row * 144 + seg * 16,
                  (const char*)g_WhH + (size_t)(jc + row) * 144 + seg * 16);
        } else if (t < 72) {
            cpa16(smb + SM_SC + buf * 512 + (t - 64) * 16,
                  (const char*)g_w2h + (size_t)jc * 2 + (t - 64) * 16);
        } else if (t < 80) {
            cpa16(smb + SM_SC + buf * 512 + 128 + (t - 72) * 16,
                  (const char*)g_b1h + (size_t)jc * 2 + (t - 72) * 16);
        } else if (t < 88) {
            cpa16(smb + SM_SC + buf * 512 + 256 + (t - 80) * 16,
                  (const char*)g_b2h + (size_t)jc * 2 + (t - 80) * 16);
        }
        CP_COMMIT();
    };

    stage(0, jb0);

    for (int c = 0; c < NCH; c++) {
        const int buf = c & 1;
        CP_WAIT0();
        __syncthreads();
        if (c + 1 < NCH) stage((c + 1) & 1, jb0 + (c + 1) * CJ);

        const int ao = SM_ADJ + buf * 34816;
        const uint32_t bw_base = smb + SM_WH + buf * 9216;
        const int sco = SM_SC + buf * 512;

#pragma unroll
        for (int kk = 0; kk < 4; kk++) {
            const int jbyte = (kk * 16 + l2) * 4;
            const int2 mA0 = *(const int2*)(sm + ao + rlA * APITCH + jbyte);
            const int2 mA1 = *(const int2*)(sm + ao + rlA * APITCH + jbyte + 32);
            const int2 mB0 = *(const int2*)(sm + ao + rlB * APITCH + jbyte);
            const int2 mB1 = *(const int2*)(sm + ao + rlB * APITCH + jbyte + 32);

            const int klo = (kk * 16 + l2) * 2, khi = klo + 16;
            const uint32_t w2lo = *(const uint32_t*)(sm + sco + klo);
            const uint32_t w2hi = *(const uint32_t*)(sm + sco + khi);
            const uint32_t b1lo = *(const uint32_t*)(sm + sco + 128 + klo);
            const uint32_t b1hi = *(const uint32_t*)(sm + sco + 128 + khi);
            const uint32_t b2lo = *(const uint32_t*)(sm + sco + 256 + klo);
            const uint32_t b2hi = *(const uint32_t*)(sm + sco + 256 + khi);

            const uint32_t MA0 = (uint32_t)mA0.x * 0x3C00u + (uint32_t)mA0.y * 0x3C000000u;
            const uint32_t MA1 = (uint32_t)mA1.x * 0x3C00u + (uint32_t)mA1.y * 0x3C000000u;
            const uint32_t MB0 = (uint32_t)mB0.x * 0x3C00u + (uint32_t)mB0.y * 0x3C000000u;
            const uint32_t MB1 = (uint32_t)mB1.x * 0x3C00u + (uint32_t)mB1.y * 0x3C000000u;

            const uint32_t rb2loA = hmul2_u(b2lo, rA2), rb2hiA = hmul2_u(b2hi, rA2);
            const uint32_t rb2loB = hmul2_u(b2lo, rB2), rb2hiB = hmul2_u(b2hi, rB2);

            const uint32_t A0 = MA0 & hgt2_mask(w2lo, th0);
            const uint32_t A1 = MB0 & hgt2_mask(w2lo, th1);
            const uint32_t A2 = MA1 & hgt2_mask(w2hi, th0);
            const uint32_t A3 = MB1 & hgt2_mask(w2hi, th1);

            uint32_t Q[4];
            Q[0] = hfma2_u(A0 ^ MA0, rb2loA, hmul2_u(A0, b1lo));
            Q[1] = hfma2_u(A1 ^ MB0, rb2loB, hmul2_u(A1, b1lo));
            Q[2] = hfma2_u(A2 ^ MA1, rb2hiA, hmul2_u(A2, b1hi));
            Q[3] = hfma2_u(A3 ^ MB1, rb2hiB, hmul2_u(A3, b1hi));

            const int krow = kk * 16 + ((l >> 3) & 1) * 8 + (l & 7);
            const uint32_t cadd = (uint32_t)((l >> 4) * 8) * 2;

#pragma unroll
            for (int nt2 = 0; nt2 < 4; nt2++) {
                uint32_t b[4];
                const uint32_t co = (uint32_t)(nt2 * 16) * 2 + cadd;
                ldsm4t(b, bw_base + (uint32_t)krow * 144 + co);
                mma16816(acc + nt2 * 8,     Q, b);
                mma16816(acc + nt2 * 8 + 4, Q, b + 2);
            }
            {   // 9th n-tile: col64 = 1.0 -> denominator
                uint32_t b[2];
                const uint32_t a8 = (uint32_t)(kk * 16 + (l & 15)) * 144 + 128;
                ldsm2t(b, bw_base + a8);
                mma16816(acc + 32, Q, b);
            }
        }
        __syncthreads();
    }

    // epilogue: write partials (col64 = denominator)
    float* baseA = g_pnum + ((size_t)js * NV + rowA) * NP;
    float* baseB = g_pnum + ((size_t)js * NV + rowB) * NP;
#pragma unroll
    for (int nt = 0; nt < 9; nt++) {
        const int col = nt * 8 + l2;
        *(float2*)(baseA + col) = make_float2(acc[nt * 4 + 0], acc[nt * 4 + 1]);
        *(float2*)(baseB + col) = make_float2(acc[nt * 4 + 2], acc[nt * 4 + 3]);
    }
}

// ---------------------------------------------------------------------------
// Kernel 4: combine j-splits, divide, elu  (float4 vectorized)
// ---------------------------------------------------------------------------
__global__ void __launch_bounds__(256) k_final(float* __restrict__ out) {
    const int idx = blockIdx.x * 256 + threadIdx.x;   // 8192*16 slots
    const int row = idx >> 4, f4 = idx & 15;
    float4 num = make_float4(0.f, 0.f, 0.f, 0.f);
    float den = 0.f;
#pragma unroll
    for (int js = 0; js < JSPL; js++) {
        const float* p = g_pnum + ((size_t)js * NV + row) * NP;
        const float4 v = *(const float4*)(p + f4 * 4);
        num.x += v.x; num.y += v.y; num.z += v.z; num.w += v.w;
        den += p[64];
    }
    const float inv = 1.0f / den;
    float4 o;
    float a0 = num.x * inv; o.x = a0 > 0.f ? a0 : expm1f(a0);
    float a1 = num.y * inv; o.y = a1 > 0.f ? a1 : expm1f(a1);
    float a2 = num.z * inv; o.z = a2 > 0.f ? a2 : expm1f(a2);
    float a3 = num.w * inv; o.w = a3 > 0.f ? a3 : expm1f(a3);
    *(float4*)(out + (size_t)row * FOUT + f4 * 4) = o;
}

// ---------------------------------------------------------------------------
extern "C" void kernel_launch(void* const* d_in, const int* in_sizes, int n_in,
                              void* d_out, int out_size) {
    const float* x   = (const float*)d_in[0];
    const int*   adj = (const int*)d_in[1];
    const float* W   = (const float*)d_in[2];
    const float* a   = (const float*)d_in[3];
    float* out = (float*)d_out;

    cudaFuncSetAttribute(k_wh,   cudaFuncAttributeMaxDynamicSharedMemorySize, SM_WHK);
    cudaFuncSetAttribute(k_main, cudaFuncAttributeMaxDynamicSharedMemorySize, SM_MAIN);

    k_wh<<<NV / 64, 256, SM_WHK>>>(x, W);
    k_prep<<<NV / 128, 128>>>(a);
    k_main<<<256, 256, SM_MAIN>>>(adj);
    k_final<<<NV * 16 / 256, 256>>>(out);
}